// round 10
// baseline (speedup 1.0000x reference)
#include <cuda_runtime.h>
#include <cuda_bf16.h>

// MoE router: scores[b,e] = st(diff+0.5)*st(0.5-diff), diff = op[b]-e, scale=20
// Closed-form 4-wide window (sigmoid saturates to 1 within 2e-9 for |x|>=20):
//   f = frac(op), k0 = floor(op)
//   A  = f*sigmoid(20f), Bv = (f-1)*sigmoid(20(f-1))
//   sc[k0-1] = A - f                         (<= 0)
//   sc[k0]   = (f+1-A) * (1+Bv-A)            (>= 0)
//   sc[k0+1] = (A-Bv)  * (1-Bv)              (>= 0)
//   sc[k0+2] = Bv                            (<= 0)
//   all other entries are 0 to <4e-9 abs.
// sigmoid(20(f-1)) = 1/(1 + e^{-20f} * e^{20}) -> reuse e0, save one EX2.
// argmax must be k0 or k0+1; strict '>' reproduces jnp.argmax first-index ties
// (at f=0.5 the closed forms are exactly symmetric: sc0 == sc1 -> k0).

#define TPB 256

__global__ void __launch_bounds__(TPB) moe_router_kernel(
    const float* __restrict__ opcode,
    float* __restrict__ out_scores,   // [B, 64]
    float* __restrict__ out_idx,      // [B] (as float)
    int B)
{
    __shared__ float4 s_w[TPB];   // per-row window values
    __shared__ int    s_k[TPB];   // per-row k0

    int t = threadIdx.x;
    int blk_base = blockIdx.x * TPB;
    int b = blk_base + t;

    // ---- Phase 1: per-row math (1 thread = 1 row), stage to smem ----
    if (b < B) {
        float op = opcode[b];
        float k0f = floorf(op);
        int k0 = (int)k0f;
        if (k0 < 0)  { k0 = 0;  k0f = 0.0f; }   // safety; op in [0,64)
        if (k0 > 63) { k0 = 63; k0f = 63.0f; }
        float f = op - k0f;   // [0,1)

        const float E20 = 485165195.4f;           // e^{20}
        float e0 = __expf(-20.0f * f);            // e^{-20f}
        float s0 = __fdividef(1.0f, 1.0f + e0);            // sigmoid(20f)
        float s1 = __fdividef(1.0f, 1.0f + e0 * E20);      // sigmoid(20(f-1))

        float A  = f * s0;
        float Bv = (f - 1.0f) * s1;

        float4 w;
        w.x = A - f;                              // e = k0-1
        w.y = (f + 1.0f - A) * (1.0f + Bv - A);   // e = k0
        w.z = (A - Bv) * (1.0f - Bv);             // e = k0+1
        w.w = Bv;                                 // e = k0+2

        s_w[t] = w;
        s_k[t] = k0;

        // argmax: only k0 / k0+1 can win; strict > = first-index ties
        int idx = k0;
        if (k0 + 1 < 64 && w.z > w.y) idx = k0 + 1;
        __stcs(out_idx + b, (float)idx);   // coalesced 4B/thread, streaming
    }
    __syncthreads();

    // ---- Phase 2: transposed, fully-coalesced row stores ----
    // Thread t owns float4-chunk c = t%16 of rows (t/16 + 16*it).
    // Each warp instruction writes 512B contiguous (2 complete rows).
    int c = t & 15;               // chunk index 0..15  (elements 4c..4c+3)
    int r0 = t >> 4;              // 0..15
    int ebase = c << 2;           // first element index of this chunk

#pragma unroll
    for (int it = 0; it < 16; it++) {
        int rlocal = r0 + (it << 4);          // 0..255
        int grow = blk_base + rlocal;
        if (grow < B) {
            float4 w = s_w[rlocal];           // LDS.128, 2-group broadcast
            int k0 = s_k[rlocal];             // LDS.32, 2-group broadcast
            int d = ebase - k0;               // element - k0 for lane 0 of chunk

            float4 v;
            v.x = (d == -1) ? w.x : (d == 0) ? w.y : (d == 1) ? w.z : (d == 2) ? w.w : 0.0f;
            int d1 = d + 1;
            v.y = (d1 == -1) ? w.x : (d1 == 0) ? w.y : (d1 == 1) ? w.z : (d1 == 2) ? w.w : 0.0f;
            int d2 = d + 2;
            v.z = (d2 == -1) ? w.x : (d2 == 0) ? w.y : (d2 == 1) ? w.z : (d2 == 2) ? w.w : 0.0f;
            int d3 = d + 3;
            v.w = (d3 == -1) ? w.x : (d3 == 0) ? w.y : (d3 == 1) ? w.z : (d3 == 2) ? w.w : 0.0f;

            // streaming store: evict-first, this data is never re-read
            __stcs((float4*)(out_scores + (size_t)grow * 64) + c, v);
        }
    }
}

extern "C" void kernel_launch(void* const* d_in, const int* in_sizes, int n_in,
                              void* d_out, int out_size)
{
    const float* opcode = (const float*)d_in[0];
    int B = in_sizes[0];
    float* out = (float*)d_out;
    float* out_scores = out;                        // [B,64] first
    // idx block is the LAST B elements of d_out; equals out + B*64 when
    // out_size == 65*B, but derive from out_size to tolerate padding.
    float* out_idx = out + ((size_t)out_size - (size_t)B);

    int blocks = (B + TPB - 1) / TPB;
    moe_router_kernel<<<blocks, TPB>>>(opcode, out_scores, out_idx, B);
}

// round 16
// speedup vs baseline: 1.3821x; 1.3821x over previous
#include <cuda_runtime.h>
#include <cuda_bf16.h>

// MoE router: scores[b,e] = st(diff+0.5)*st(0.5-diff), diff = op[b]-e, scale=20
// Closed-form 4-wide window (sigmoid saturates to 1 within 2e-9 for |x|>=20):
//   f = frac(op), k0 = floor(op)
//   A  = f*sigmoid(20f), Bv = (f-1)*sigmoid(20(f-1))
//   sc[k0-1] = A - f ; sc[k0] = (f+1-A)(1+Bv-A) ; sc[k0+1] = (A-Bv)(1-Bv) ; sc[k0+2] = Bv
//   all other entries are 0 to <4e-9 abs.
// The window spans at most two aligned float4 chunks c0=(k0-1)>>2 and c0+1.
// Phase 1 builds those two vectors ONCE per row; phase 2 is a lean
// broadcast-load + 2-way compare + coalesced STG.128 stream.
// argmax must be k0 or k0+1; strict '>' reproduces jnp.argmax first-index ties.

#define TPB 256

__global__ void __launch_bounds__(TPB) moe_router_kernel(
    const float* __restrict__ opcode,
    float* __restrict__ out_scores,   // [B, 64]
    float* __restrict__ out_idx,      // [B] (as float)
    int B)
{
    __shared__ float4 s_v0[TPB];   // window chunk at c0
    __shared__ float4 s_v1[TPB];   // window chunk at c0+1
    __shared__ int    s_c0[TPB];   // c0 (may be -1; then only c1 matches)

    int t = threadIdx.x;
    int blk_base = blockIdx.x * TPB;
    int b = blk_base + t;

    // ---- Phase 1: per-row math + window chunk construction ----
    if (b < B) {
        float op = opcode[b];
        float k0f = floorf(op);
        int k0 = (int)k0f;
        if (k0 < 0)  { k0 = 0;  k0f = 0.0f; }   // safety; op in [0,64)
        if (k0 > 63) { k0 = 63; k0f = 63.0f; }
        float f = op - k0f;   // [0,1)

        const float E20 = 485165195.4f;           // e^{20}
        float e0 = __expf(-20.0f * f);            // e^{-20f}
        float s0 = __fdividef(1.0f, 1.0f + e0);            // sigmoid(20f)
        float s1 = __fdividef(1.0f, 1.0f + e0 * E20);      // sigmoid(20(f-1))

        float A  = f * s0;
        float Bv = (f - 1.0f) * s1;

        float wx = A - f;                              // e = k0-1
        float wy = (f + 1.0f - A) * (1.0f + Bv - A);   // e = k0
        float wz = (A - Bv) * (1.0f - Bv);             // e = k0+1
        float ww = Bv;                                 // e = k0+2

        // window occupies elements k0-1 .. k0+2; o = offset within chunk c0
        int o  = (k0 - 1) & 3;        // k0=0 -> 3 (two's complement)
        int c0 = (k0 - 1 - o) >> 2;   // k0=0 -> -1 (never matches a chunk)

        float arr[8];
#pragma unroll
        for (int j = 0; j < 8; j++) {
            int jo = j - o;
            arr[j] = (jo == 0) ? wx : (jo == 1) ? wy :
                     (jo == 2) ? wz : (jo == 3) ? ww : 0.0f;
        }
        s_v0[t] = make_float4(arr[0], arr[1], arr[2], arr[3]);
        s_v1[t] = make_float4(arr[4], arr[5], arr[6], arr[7]);
        s_c0[t] = c0;

        // argmax: only k0 / k0+1 can win; strict > = first-index ties
        int idx = k0;
        if (k0 + 1 < 64 && wz > wy) idx = k0 + 1;
        __stcs(out_idx + b, (float)idx);   // coalesced, streaming
    }
    __syncthreads();

    // ---- Phase 2: transposed, fully-coalesced row stores ----
    // Thread t owns chunk c = t%16 of rows (t/16 + 16*it); each warp STG
    // writes 512B contiguous (2 complete rows).
    int c  = t & 15;
    int r0 = t >> 4;

#pragma unroll
    for (int it = 0; it < 16; it++) {
        int rlocal = r0 + (it << 4);          // 0..255
        int grow = blk_base + rlocal;
        if (grow < B) {
            int c0 = s_c0[rlocal];            // LDS.32, 2-addr broadcast
            float4 v = make_float4(0.0f, 0.0f, 0.0f, 0.0f);
            if (c == c0)      v = s_v0[rlocal];   // LDS.128 broadcast
            else if (c == c0 + 1) v = s_v1[rlocal];
            __stcs((float4*)(out_scores + (size_t)grow * 64) + c, v);
        }
    }
}

extern "C" void kernel_launch(void* const* d_in, const int* in_sizes, int n_in,
                              void* d_out, int out_size)
{
    const float* opcode = (const float*)d_in[0];
    int B = in_sizes[0];
    float* out = (float*)d_out;
    float* out_scores = out;                        // [B,64] first
    // idx block is the LAST B elements of d_out (== out + 64*B when unpadded)
    float* out_idx = out + ((size_t)out_size - (size_t)B);

    int blocks = (B + TPB - 1) / TPB;
    moe_router_kernel<<<blocks, TPB>>>(opcode, out_scores, out_idx, B);
}